// round 12
// baseline (speedup 1.0000x reference)
#include <cuda_runtime.h>
#include <math.h>

// Problem constants
#define Bv 8
#define Dv 128
#define Mv 1024
#define INVT 14.285714285714286f   // 1/0.07

// GEMM tiling
#define TJ 128
#define TI 128
#define KC 32            // k-chunk held in shared
#define SPLIT 8
#define THREADS 256
#define NFIN 32          // finalize stage-1 blocks

typedef unsigned long long u64;

// Scratch (device globals; allocation-free)
__device__ __align__(16) float g_f0t[Bv * Dv * Mv];   // [b][k][m], L2-normalized
__device__ __align__(16) float g_f1t[Bv * Dv * Mv];   // [b][k][m], L2-normalized * (1/T)
__device__ __align__(16) float g_diag[Bv * Mv];       // diagonal logits l_jj
__device__ __align__(16) float g_part[SPLIT][Bv * Mv];// partial exp-sums per column
__device__ float g_bsum[NFIN];                        // finalize stage-1 partials
__device__ int g_idx64;                               // 1 if corrs is int64

// ---------------------------------------------------------------------------
// Packed fp32x2 helpers (Blackwell FFMA2 path, PTX-only)
// ---------------------------------------------------------------------------
__device__ __forceinline__ void fma2(u64& c, u64 a, u64 b) {
    asm("fma.rn.f32x2 %0, %1, %2, %3;" : "=l"(c) : "l"(a), "l"(b), "l"(c));
}
__device__ __forceinline__ u64 dup2(float x) {
    u64 r; unsigned xi = __float_as_uint(x);
    asm("mov.b64 %0, {%1, %1};" : "=l"(r) : "r"(xi));
    return r;
}
__device__ __forceinline__ float2 unpack2(u64 v) {
    unsigned lo, hi;
    asm("mov.b64 {%0, %1}, %2;" : "=r"(lo), "=r"(hi) : "l"(v));
    return make_float2(__uint_as_float(lo), __uint_as_float(hi));
}

// ---------------------------------------------------------------------------
// Kernel 0: detect corrs dtype (int64 vs int32). First 8192 u64 words (64 KB)
// are in-bounds under both dtypes (int32 buffer is exactly 64 KB).
// ---------------------------------------------------------------------------
__global__ void detect_dtype_kernel(const u64* __restrict__ corrs, int N) {
    __shared__ int flag;
    if (threadIdx.x == 0) flag = 1;
    __syncthreads();
    for (int i = threadIdx.x; i < 8192; i += 256)
        if (corrs[i] >= (u64)N) flag = 0;
    __syncthreads();
    if (threadIdx.x == 0) g_idx64 = flag;
}

// ---------------------------------------------------------------------------
// Kernel 1: gather selected rows, L2-normalize, store transposed (k-major).
// One warp per row. 2*B*M = 16384 rows.
// ---------------------------------------------------------------------------
__global__ void gather_norm_kernel(const float* __restrict__ feats0,
                                   const float* __restrict__ feats1,
                                   const void* __restrict__ corrs,
                                   int N) {
    int warp = (blockIdx.x * blockDim.x + threadIdx.x) >> 5;
    int lane = threadIdx.x & 31;
    if (warp >= 2 * Bv * Mv) return;

    int half = warp / (Bv * Mv);
    int rr   = warp % (Bv * Mv);
    int b    = rr >> 10;
    int m    = rr & (Mv - 1);

    long long idx;
    int ci = rr * 2 + half;
    if (g_idx64) idx = ((const long long*)corrs)[ci];
    else         idx = (long long)((const int*)corrs)[ci];

    const float* __restrict__ src =
        (half == 0 ? feats0 : feats1) + ((long long)b * N + idx) * Dv;

    float4 v = *(const float4*)(src + lane * 4);
    float ss = v.x * v.x + v.y * v.y + v.z * v.z + v.w * v.w;
#pragma unroll
    for (int o = 16; o > 0; o >>= 1) ss += __shfl_xor_sync(0xffffffffu, ss, o);

    float scale = 1.0f / fmaxf(sqrtf(ss), 1e-12f);
    if (half) scale *= INVT;

    float* __restrict__ dst = (half == 0 ? g_f0t : g_f1t) + b * (Dv * Mv);
    int k = lane * 4;
    dst[(k + 0) * Mv + m] = v.x * scale;
    dst[(k + 1) * Mv + m] = v.y * scale;
    dst[(k + 2) * Mv + m] = v.z * scale;
    dst[(k + 3) * Mv + m] = v.w * scale;
}

// ---------------------------------------------------------------------------
// Kernel 2: fused 128x128 logits tile GEMM (packed f32x2 FMA) + column
// exp-sum with fixed shift C=1/T + diagonal capture.
// grid = (M/TJ, SPLIT, B), 256 threads, 8x8 microtile as 8x4 f32x2 pairs.
// ---------------------------------------------------------------------------
__global__ void __launch_bounds__(THREADS, 2)
logits_lse_kernel() {
    __shared__ __align__(16) float sA[KC * TI];   // [k][i]  16 KB
    __shared__ __align__(16) float sB[KC * TJ];   // [k][j]  16 KB

    const int t  = threadIdx.x;
    const int j0 = blockIdx.x * TJ;
    const int sp = blockIdx.y;
    const int b  = blockIdx.z;
    const int ibase = sp * (Mv / SPLIT);          // 128-row i stripe

    const float* __restrict__ F0 = g_f0t + b * (Dv * Mv);
    const float* __restrict__ F1 = g_f1t + b * (Dv * Mv);

    const int tx = t & 15;              // j-group: j = j0 + tx*8 + jj
    const int ty = t >> 4;              // i-group: i = ibase + ty*8 + ii

    u64 c2[8][4];
#pragma unroll
    for (int ii = 0; ii < 8; ii++)
#pragma unroll
        for (int jp = 0; jp < 4; jp++) c2[ii][jp] = 0ull;

    for (int kc = 0; kc < Dv / KC; kc++) {
        __syncthreads();                // previous chunk fully consumed
        // load 32 k-rows x 32 float4 per tile; 4 float4 per thread per tile
#pragma unroll
        for (int r = 0; r < 4; r++) {
            int v = t + r * THREADS;    // 0..1023
            int k = v >> 5, q = v & 31;
            const float* pa = F1 + (kc * KC + k) * Mv + ibase + q * 4;
            const float* pb = F0 + (kc * KC + k) * Mv + j0 + q * 4;
            *(float4*)(sA + k * TI + q * 4) = *(const float4*)pa;
            *(float4*)(sB + k * TJ + q * 4) = *(const float4*)pb;
        }
        __syncthreads();

#pragma unroll 4
        for (int k = 0; k < KC; k++) {
            float4 a0 = *(const float4*)(sA + k * TI + ty * 8);
            float4 a1 = *(const float4*)(sA + k * TI + ty * 8 + 4);
            ulonglong2 b0 = *(const ulonglong2*)(sB + k * TJ + tx * 8);
            ulonglong2 b1 = *(const ulonglong2*)(sB + k * TJ + tx * 8 + 4);
            u64 bp[4] = {b0.x, b0.y, b1.x, b1.y};
            float av[8] = {a0.x, a0.y, a0.z, a0.w, a1.x, a1.y, a1.z, a1.w};
#pragma unroll
            for (int ii = 0; ii < 8; ii++) {
                u64 ad = dup2(av[ii]);
#pragma unroll
                for (int jp = 0; jp < 4; jp++) fma2(c2[ii][jp], ad, bp[jp]);
            }
        }
    }

    // Epilogue: exp-accumulate per column + diagonal capture
    float esum[8];
#pragma unroll
    for (int jj = 0; jj < 8; jj++) esum[jj] = 0.f;
#pragma unroll
    for (int ii = 0; ii < 8; ii++) {
        int ig = ibase + ty * 8 + ii;
#pragma unroll
        for (int jp = 0; jp < 4; jp++) {
            float2 l = unpack2(c2[ii][jp]);
            int jg0 = j0 + tx * 8 + jp * 2;
            esum[jp * 2 + 0] += __expf(l.x - INVT);
            esum[jp * 2 + 1] += __expf(l.y - INVT);
            if (ig == jg0)     g_diag[b * Mv + jg0]     = l.x;
            if (ig == jg0 + 1) g_diag[b * Mv + jg0 + 1] = l.y;
        }
    }

    // Cross-ty reduction via reused sA: red[16][128]
    __syncthreads();
    float* red = sA;
#pragma unroll
    for (int jj = 0; jj < 8; jj++) red[ty * TJ + tx * 8 + jj] = esum[jj];
    __syncthreads();
    if (t < TJ) {
        float s = 0.f;
#pragma unroll
        for (int q = 0; q < 16; q++) s += red[q * TJ + t];
        g_part[sp][b * Mv + j0 + t] = s;
    }
}

// ---------------------------------------------------------------------------
// Kernel 3a: per-column loss, 32 blocks x 256 threads (one column/thread).
// ---------------------------------------------------------------------------
__global__ void finalize1_kernel() {
    __shared__ float red[256];
    int t = threadIdx.x;
    int col = blockIdx.x * 256 + t;
    float cs = 0.f;
#pragma unroll
    for (int p = 0; p < SPLIT; p++) cs += g_part[p][col];
    red[t] = INVT + logf(cs) - g_diag[col];
    __syncthreads();
    for (int o = 128; o > 0; o >>= 1) {
        if (t < o) red[t] += red[t + o];
        __syncthreads();
    }
    if (t == 0) g_bsum[blockIdx.x] = red[0];
}

// Kernel 3b: sum 32 partials -> loss
__global__ void finalize2_kernel(float* __restrict__ out) {
    int t = threadIdx.x;
    float s = (t < NFIN) ? g_bsum[t] : 0.f;
#pragma unroll
    for (int o = 16; o > 0; o >>= 1) s += __shfl_xor_sync(0xffffffffu, s, o);
    if (t == 0) out[0] = s * (1.0f / (float)(Bv * Mv));
}

// ---------------------------------------------------------------------------
extern "C" void kernel_launch(void* const* d_in, const int* in_sizes, int n_in,
                              void* d_out, int out_size) {
    const float* feats0 = (const float*)d_in[0];
    const float* feats1 = (const float*)d_in[1];
    const void*  corrs  = (const void*)d_in[2];
    int N = in_sizes[0] / (Bv * Dv);    // 20000

    detect_dtype_kernel<<<1, 256>>>((const u64*)corrs, N);
    gather_norm_kernel<<<(2 * Bv * Mv) / 8, 256>>>(feats0, feats1, corrs, N);

    dim3 g2(Mv / TJ, SPLIT, Bv);        // 8 x 8 x 8 = 512 blocks
    logits_lse_kernel<<<g2, THREADS>>>();

    finalize1_kernel<<<NFIN, 256>>>();
    finalize2_kernel<<<1, 32>>>((float*)d_out);
}

// round 13
// speedup vs baseline: 1.5204x; 1.5204x over previous
#include <cuda_runtime.h>
#include <math.h>

// Problem constants
#define Bv 8
#define Dv 128
#define Mv 1024
#define INVT 14.285714285714286f   // 1/0.07

// GEMM tiling
#define TJ 128
#define TI 128
#define KC 32            // k-chunk held in shared
#define SPLIT 8
#define THREADS 256
#define NFIN 32          // finalize stage-1 blocks

typedef unsigned long long u64;

// Scratch (device globals; allocation-free)
__device__ __align__(16) float g_f0t[Bv * Dv * Mv];   // [b][k][m], L2-normalized
__device__ __align__(16) float g_f1t[Bv * Dv * Mv];   // [b][k][m], L2-normalized * (1/T)
__device__ __align__(16) float g_diag[Bv * Mv];       // diagonal logits l_jj
__device__ __align__(16) float g_part[SPLIT][Bv * Mv];// partial exp-sums per column
__device__ float g_bsum[NFIN];                        // finalize stage-1 partials
__device__ int g_idx64;                               // 1 if corrs is int64

// ---------------------------------------------------------------------------
// Packed fp32x2 helpers (Blackwell FFMA2 path, PTX-only)
// ---------------------------------------------------------------------------
__device__ __forceinline__ void fma2(u64& c, u64 a, u64 b) {
    asm("fma.rn.f32x2 %0, %1, %2, %3;" : "=l"(c) : "l"(a), "l"(b), "l"(c));
}
__device__ __forceinline__ u64 dup2(float x) {
    u64 r; unsigned xi = __float_as_uint(x);
    asm("mov.b64 %0, {%1, %1};" : "=l"(r) : "r"(xi));
    return r;
}
__device__ __forceinline__ float2 unpack2(u64 v) {
    unsigned lo, hi;
    asm("mov.b64 {%0, %1}, %2;" : "=r"(lo), "=r"(hi) : "l"(v));
    return make_float2(__uint_as_float(lo), __uint_as_float(hi));
}

// ---------------------------------------------------------------------------
// Kernel 0: detect corrs dtype (int64 vs int32). First 8192 u64 words (64 KB)
// are in-bounds under both dtypes (int32 buffer is exactly 64 KB).
// ---------------------------------------------------------------------------
__global__ void detect_dtype_kernel(const u64* __restrict__ corrs, int N) {
    __shared__ int flag;
    if (threadIdx.x == 0) flag = 1;
    __syncthreads();
    for (int i = threadIdx.x; i < 8192; i += 256)
        if (corrs[i] >= (u64)N) flag = 0;
    __syncthreads();
    if (threadIdx.x == 0) g_idx64 = flag;
}

// ---------------------------------------------------------------------------
// Kernel 1: gather selected rows, L2-normalize, store transposed (k-major).
// One warp per row. 2*B*M = 16384 rows.
// ---------------------------------------------------------------------------
__global__ void gather_norm_kernel(const float* __restrict__ feats0,
                                   const float* __restrict__ feats1,
                                   const void* __restrict__ corrs,
                                   int N) {
    int warp = (blockIdx.x * blockDim.x + threadIdx.x) >> 5;
    int lane = threadIdx.x & 31;
    if (warp >= 2 * Bv * Mv) return;

    int half = warp / (Bv * Mv);
    int rr   = warp % (Bv * Mv);
    int b    = rr >> 10;
    int m    = rr & (Mv - 1);

    long long idx;
    int ci = rr * 2 + half;
    if (g_idx64) idx = ((const long long*)corrs)[ci];
    else         idx = (long long)((const int*)corrs)[ci];

    const float* __restrict__ src =
        (half == 0 ? feats0 : feats1) + ((long long)b * N + idx) * Dv;

    float4 v = *(const float4*)(src + lane * 4);
    float ss = v.x * v.x + v.y * v.y + v.z * v.z + v.w * v.w;
#pragma unroll
    for (int o = 16; o > 0; o >>= 1) ss += __shfl_xor_sync(0xffffffffu, ss, o);

    float scale = 1.0f / fmaxf(sqrtf(ss), 1e-12f);
    if (half) scale *= INVT;

    float* __restrict__ dst = (half == 0 ? g_f0t : g_f1t) + b * (Dv * Mv);
    int k = lane * 4;
    dst[(k + 0) * Mv + m] = v.x * scale;
    dst[(k + 1) * Mv + m] = v.y * scale;
    dst[(k + 2) * Mv + m] = v.z * scale;
    dst[(k + 3) * Mv + m] = v.w * scale;
}

// ---------------------------------------------------------------------------
// Kernel 2: fused 128x128 logits tile GEMM (packed f32x2 FMA) + column
// exp-sum with fixed shift C=1/T + diagonal capture.
// grid = (M/TJ, SPLIT, B), 256 threads, 8x8 microtile as 8x4 f32x2 pairs.
// ---------------------------------------------------------------------------
__global__ void __launch_bounds__(THREADS, 2)
logits_lse_kernel() {
    __shared__ __align__(16) float sA[KC * TI];   // [k][i]  16 KB
    __shared__ __align__(16) float sB[KC * TJ];   // [k][j]  16 KB

    const int t  = threadIdx.x;
    const int j0 = blockIdx.x * TJ;
    const int sp = blockIdx.y;
    const int b  = blockIdx.z;
    const int ibase = sp * (Mv / SPLIT);          // 128-row i stripe

    const float* __restrict__ F0 = g_f0t + b * (Dv * Mv);
    const float* __restrict__ F1 = g_f1t + b * (Dv * Mv);

    const int tx = t & 15;              // j-group: j = j0 + tx*8 + jj
    const int ty = t >> 4;              // i-group: i = ibase + ty*8 + ii

    u64 c2[8][4];
#pragma unroll
    for (int ii = 0; ii < 8; ii++)
#pragma unroll
        for (int jp = 0; jp < 4; jp++) c2[ii][jp] = 0ull;

    for (int kc = 0; kc < Dv / KC; kc++) {
        __syncthreads();                // previous chunk fully consumed
        // load 32 k-rows x 32 float4 per tile; 4 float4 per thread per tile
#pragma unroll
        for (int r = 0; r < 4; r++) {
            int v = t + r * THREADS;    // 0..1023
            int k = v >> 5, q = v & 31;
            const float* pa = F1 + (kc * KC + k) * Mv + ibase + q * 4;
            const float* pb = F0 + (kc * KC + k) * Mv + j0 + q * 4;
            *(float4*)(sA + k * TI + q * 4) = *(const float4*)pa;
            *(float4*)(sB + k * TJ + q * 4) = *(const float4*)pb;
        }
        __syncthreads();

#pragma unroll 4
        for (int k = 0; k < KC; k++) {
            float4 a0 = *(const float4*)(sA + k * TI + ty * 8);
            float4 a1 = *(const float4*)(sA + k * TI + ty * 8 + 4);
            ulonglong2 b0 = *(const ulonglong2*)(sB + k * TJ + tx * 8);
            ulonglong2 b1 = *(const ulonglong2*)(sB + k * TJ + tx * 8 + 4);
            u64 bp[4] = {b0.x, b0.y, b1.x, b1.y};
            float av[8] = {a0.x, a0.y, a0.z, a0.w, a1.x, a1.y, a1.z, a1.w};
#pragma unroll
            for (int ii = 0; ii < 8; ii++) {
                u64 ad = dup2(av[ii]);
#pragma unroll
                for (int jp = 0; jp < 4; jp++) fma2(c2[ii][jp], ad, bp[jp]);
            }
        }
    }

    // Epilogue: exp-accumulate per column + diagonal capture
    float esum[8];
#pragma unroll
    for (int jj = 0; jj < 8; jj++) esum[jj] = 0.f;
#pragma unroll
    for (int ii = 0; ii < 8; ii++) {
        int ig = ibase + ty * 8 + ii;
#pragma unroll
        for (int jp = 0; jp < 4; jp++) {
            float2 l = unpack2(c2[ii][jp]);
            int jg0 = j0 + tx * 8 + jp * 2;
            esum[jp * 2 + 0] += __expf(l.x - INVT);
            esum[jp * 2 + 1] += __expf(l.y - INVT);
            if (ig == jg0)     g_diag[b * Mv + jg0]     = l.x;
            if (ig == jg0 + 1) g_diag[b * Mv + jg0 + 1] = l.y;
        }
    }

    // Cross-ty reduction via reused sA: red[16][128]
    __syncthreads();
    float* red = sA;
#pragma unroll
    for (int jj = 0; jj < 8; jj++) red[ty * TJ + tx * 8 + jj] = esum[jj];
    __syncthreads();
    if (t < TJ) {
        float s = 0.f;
#pragma unroll
        for (int q = 0; q < 16; q++) s += red[q * TJ + t];
        g_part[sp][b * Mv + j0 + t] = s;
    }
}

// ---------------------------------------------------------------------------
// Kernel 3a: per-column loss, 32 blocks x 256 threads (one column/thread).
// ---------------------------------------------------------------------------
__global__ void finalize1_kernel() {
    __shared__ float red[256];
    int t = threadIdx.x;
    int col = blockIdx.x * 256 + t;
    float cs = 0.f;
#pragma unroll
    for (int p = 0; p < SPLIT; p++) cs += g_part[p][col];
    red[t] = INVT + logf(cs) - g_diag[col];
    __syncthreads();
    for (int o = 128; o > 0; o >>= 1) {
        if (t < o) red[t] += red[t + o];
        __syncthreads();
    }
    if (t == 0) g_bsum[blockIdx.x] = red[0];
}

// Kernel 3b: sum 32 partials -> loss
__global__ void finalize2_kernel(float* __restrict__ out) {
    int t = threadIdx.x;
    float s = (t < NFIN) ? g_bsum[t] : 0.f;
#pragma unroll
    for (int o = 16; o > 0; o >>= 1) s += __shfl_xor_sync(0xffffffffu, s, o);
    if (t == 0) out[0] = s * (1.0f / (float)(Bv * Mv));
}

// ---------------------------------------------------------------------------
extern "C" void kernel_launch(void* const* d_in, const int* in_sizes, int n_in,
                              void* d_out, int out_size) {
    const float* feats0 = (const float*)d_in[0];
    const float* feats1 = (const float*)d_in[1];
    const void*  corrs  = (const void*)d_in[2];
    int N = in_sizes[0] / (Bv * Dv);    // 20000

    detect_dtype_kernel<<<1, 256>>>((const u64*)corrs, N);
    gather_norm_kernel<<<(2 * Bv * Mv) / 8, 256>>>(feats0, feats1, corrs, N);

    dim3 g2(Mv / TJ, SPLIT, Bv);        // 8 x 8 x 8 = 512 blocks
    logits_lse_kernel<<<g2, THREADS>>>();

    finalize1_kernel<<<NFIN, 256>>>();
    finalize2_kernel<<<1, 32>>>((float*)d_out);
}

// round 17
// speedup vs baseline: 4.6197x; 3.0384x over previous
#include <cuda_runtime.h>
#include <cuda_bf16.h>
#include <math.h>
#include <stdint.h>

// Problem constants
#define Bv 8
#define Dv 128
#define Mv 1024
#define INVT 14.285714285714286f   // 1/0.07

#define THREADS 256
#define NIT 8                      // i-tiles of 128
#define NFIN 32
typedef unsigned long long u64;

// Dynamic smem layout for kernel 2
#define SM_A   0                   // 128x128 bf16, swizzled (32 KB)
#define SM_B   32768               // 128x128 bf16, swizzled (32 KB)
#define SM_RED 65536               // float[2][128] (1 KB)
#define SMEM_TOTAL 66560

// Scratch (device globals; allocation-free)
__device__ __align__(16) __nv_bfloat16 g_f0r[Bv * Mv * Dv]; // [b*M+m][k] normalized
__device__ __align__(16) __nv_bfloat16 g_f1r[Bv * Mv * Dv]; // [b*M+m][k] normalized * 1/T
__device__ __align__(16) float g_diag[Bv * Mv];
__device__ __align__(16) float g_part[NIT][Bv * Mv];
__device__ float g_bsum[NFIN];
__device__ int g_idx64;

// ---------------------------------------------------------------------------
// Helpers
// ---------------------------------------------------------------------------
__device__ __forceinline__ uint32_t smem_u32(const void* p) {
    uint32_t a;
    asm("{ .reg .u64 t; cvta.to.shared.u64 t, %1; cvt.u32.u64 %0, t; }" : "=r"(a) : "l"(p));
    return a;
}
// Swizzled byte offset: row r (0..127, 256B rows), 16B chunk q (0..15)
__device__ __forceinline__ uint32_t swz(int r, int q) {
    return (uint32_t)(r * 256 + ((q ^ (r & 7)) << 4));
}
__device__ __forceinline__ void ldsm_x4(uint32_t& r0, uint32_t& r1,
                                        uint32_t& r2, uint32_t& r3, uint32_t addr) {
    asm volatile("ldmatrix.sync.aligned.m8n8.x4.shared.b16 {%0,%1,%2,%3}, [%4];"
                 : "=r"(r0), "=r"(r1), "=r"(r2), "=r"(r3) : "r"(addr));
}
__device__ __forceinline__ void mma_bf16(float* d, const uint32_t* a, uint32_t b0, uint32_t b1) {
    asm volatile("mma.sync.aligned.m16n8k16.row.col.f32.bf16.bf16.f32 "
                 "{%0,%1,%2,%3},{%4,%5,%6,%7},{%8,%9},{%0,%1,%2,%3};"
                 : "+f"(d[0]), "+f"(d[1]), "+f"(d[2]), "+f"(d[3])
                 : "r"(a[0]), "r"(a[1]), "r"(a[2]), "r"(a[3]), "r"(b0), "r"(b1));
}

// ---------------------------------------------------------------------------
// Kernel 0: corrs dtype detection (int64 vs int32)
// ---------------------------------------------------------------------------
__global__ void detect_dtype_kernel(const u64* __restrict__ corrs, int N) {
    __shared__ int flag;
    if (threadIdx.x == 0) flag = 1;
    __syncthreads();
    for (int i = threadIdx.x; i < 8192; i += 256)
        if (corrs[i] >= (u64)N) flag = 0;
    __syncthreads();
    if (threadIdx.x == 0) g_idx64 = flag;
}

// ---------------------------------------------------------------------------
// Kernel 1: gather + L2-normalize + bf16 convert, row-major output.
// One warp per row; 16384 rows.
// ---------------------------------------------------------------------------
__global__ void gather_norm_kernel(const float* __restrict__ feats0,
                                   const float* __restrict__ feats1,
                                   const void* __restrict__ corrs, int N) {
    int warp = (blockIdx.x * blockDim.x + threadIdx.x) >> 5;
    int lane = threadIdx.x & 31;
    if (warp >= 2 * Bv * Mv) return;

    int half = warp / (Bv * Mv);
    int rr   = warp % (Bv * Mv);          // b*M + m
    int b    = rr >> 10;

    long long idx;
    int ci = rr * 2 + half;
    if (g_idx64) idx = ((const long long*)corrs)[ci];
    else         idx = (long long)((const int*)corrs)[ci];

    const float* __restrict__ src =
        (half == 0 ? feats0 : feats1) + ((long long)b * N + idx) * Dv;

    float4 v = *(const float4*)(src + lane * 4);
    float ss = v.x * v.x + v.y * v.y + v.z * v.z + v.w * v.w;
#pragma unroll
    for (int o = 16; o > 0; o >>= 1) ss += __shfl_xor_sync(0xffffffffu, ss, o);

    float scale = 1.0f / fmaxf(sqrtf(ss), 1e-12f);
    if (half) scale *= INVT;

    __nv_bfloat16* __restrict__ dst = (half == 0 ? g_f0r : g_f1r) + (size_t)rr * Dv;
    __nv_bfloat162 p0, p1;
    p0.x = __float2bfloat16_rn(v.x * scale);
    p0.y = __float2bfloat16_rn(v.y * scale);
    p1.x = __float2bfloat16_rn(v.z * scale);
    p1.y = __float2bfloat16_rn(v.w * scale);
    uint2 pk = make_uint2(*(uint32_t*)&p0, *(uint32_t*)&p1);
    *(uint2*)(dst + lane * 4) = pk;
}

// ---------------------------------------------------------------------------
// Kernel 2: bf16 mma.sync GEMM (128x128x128 tile) + fused exp epilogue.
// grid = (jq=8, it=8, b=8) = 512 CTAs. 8 warps: 2 (i) x 4 (j), warp tile 64x32.
// ---------------------------------------------------------------------------
__global__ void __launch_bounds__(THREADS, 2)
logits_lse_kernel() {
    extern __shared__ char sm[];
    const uint32_t smb = smem_u32(sm);

    const int t    = threadIdx.x;
    const int wid  = t >> 5;
    const int lane = t & 31;
    const int wi   = wid & 1;            // i-warp (0..1), 64 rows each
    const int wj   = wid >> 1;           // j-warp (0..3), 32 cols each
    const int jq   = blockIdx.x;
    const int it   = blockIdx.y;
    const int b    = blockIdx.z;

    // Load A (f1 rows) and B (f0 rows), both K-major, swizzled.
    const __nv_bfloat16* __restrict__ F1 = g_f1r + ((size_t)b * Mv + it * 128) * Dv;
    const __nv_bfloat16* __restrict__ F0 = g_f0r + ((size_t)b * Mv + jq * 128) * Dv;
#pragma unroll
    for (int i = 0; i < 8; i++) {
        int v = t + i * THREADS;         // 0..2047
        int r = v >> 4, q = v & 15;
        *(uint4*)(sm + SM_A + swz(r, q)) = ((const uint4*)(F1 + r * Dv))[q];
        *(uint4*)(sm + SM_B + swz(r, q)) = ((const uint4*)(F0 + r * Dv))[q];
    }
    __syncthreads();

    float d[4][4][4];
#pragma unroll
    for (int m = 0; m < 4; m++)
#pragma unroll
        for (int n = 0; n < 4; n++)
#pragma unroll
            for (int v = 0; v < 4; v++) d[m][n][v] = 0.f;

    // ldmatrix lane addressing: x4 matrices = (rows0-7,k0-7),(rows8-15,k0-7),
    // (rows0-7,k8-15),(rows8-15,k8-15)
    const int lr = (lane & 7) + ((lane >> 3) & 1) * 8;  // row within 16
    const int kh = lane >> 4;                            // k-half chunk

#pragma unroll
    for (int ks = 0; ks < 8; ks++) {
        uint32_t a[4][4], bb[2][4];
#pragma unroll
        for (int m = 0; m < 4; m++)
            ldsm_x4(a[m][0], a[m][1], a[m][2], a[m][3],
                    smb + SM_A + swz(wi * 64 + m * 16 + lr, ks * 2 + kh));
#pragma unroll
        for (int nb = 0; nb < 2; nb++)
            ldsm_x4(bb[nb][0], bb[nb][1], bb[nb][2], bb[nb][3],
                    smb + SM_B + swz(wj * 32 + nb * 16 + lr, ks * 2 + kh));
#pragma unroll
        for (int m = 0; m < 4; m++)
#pragma unroll
            for (int n = 0; n < 4; n++)
                mma_bf16(d[m][n], a[m],
                         bb[n >> 1][n & 1], bb[n >> 1][2 + (n & 1)]);
    }

    // Epilogue: exp-accumulate per column + diagonal capture (all in regs)
    float e[4][2];
#pragma unroll
    for (int n = 0; n < 4; n++) { e[n][0] = 0.f; e[n][1] = 0.f; }

#pragma unroll
    for (int m = 0; m < 4; m++) {
        int r0 = it * 128 + wi * 64 + m * 16 + (lane >> 2);
        int r1 = r0 + 8;
#pragma unroll
        for (int n = 0; n < 4; n++) {
            int c0 = jq * 128 + wj * 32 + n * 8 + (lane & 3) * 2;
            float d0 = d[m][n][0], d1 = d[m][n][1], d2 = d[m][n][2], d3 = d[m][n][3];
            if (r0 == c0)     g_diag[b * Mv + c0]     = d0;
            if (r0 == c0 + 1) g_diag[b * Mv + c0 + 1] = d1;
            if (r1 == c0)     g_diag[b * Mv + c0]     = d2;
            if (r1 == c0 + 1) g_diag[b * Mv + c0 + 1] = d3;
            e[n][0] += __expf(d0 - INVT) + __expf(d2 - INVT);
            e[n][1] += __expf(d1 - INVT) + __expf(d3 - INVT);
        }
    }
    // lanes sharing a column differ in bits 2-4 -> butterfly reduce
#pragma unroll
    for (int n = 0; n < 4; n++)
#pragma unroll
        for (int h = 0; h < 2; h++) {
            float v = e[n][h];
            v += __shfl_xor_sync(0xffffffffu, v, 4);
            v += __shfl_xor_sync(0xffffffffu, v, 8);
            v += __shfl_xor_sync(0xffffffffu, v, 16);
            e[n][h] = v;
        }
    float* red = (float*)(sm + SM_RED);  // [2][128]
    if (lane < 4) {
#pragma unroll
        for (int n = 0; n < 4; n++) {
            red[wi * 128 + wj * 32 + n * 8 + lane * 2 + 0] = e[n][0];
            red[wi * 128 + wj * 32 + n * 8 + lane * 2 + 1] = e[n][1];
        }
    }
    __syncthreads();
    if (t < 128)
        g_part[it][b * Mv + jq * 128 + t] = red[t] + red[128 + t];
}

// ---------------------------------------------------------------------------
// Kernel 3a: per-column loss, 32 blocks x 256 threads (one column/thread)
// ---------------------------------------------------------------------------
__global__ void finalize1_kernel() {
    __shared__ float red[256];
    int t = threadIdx.x;
    int col = blockIdx.x * 256 + t;
    float cs = 0.f;
#pragma unroll
    for (int p = 0; p < NIT; p++) cs += g_part[p][col];
    red[t] = INVT + logf(cs) - g_diag[col];
    __syncthreads();
    for (int o = 128; o > 0; o >>= 1) {
        if (t < o) red[t] += red[t + o];
        __syncthreads();
    }
    if (t == 0) g_bsum[blockIdx.x] = red[0];
}

// Kernel 3b: sum 32 partials -> loss
__global__ void finalize2_kernel(float* __restrict__ out) {
    int t = threadIdx.x;
    float s = (t < NFIN) ? g_bsum[t] : 0.f;
#pragma unroll
    for (int o = 16; o > 0; o >>= 1) s += __shfl_xor_sync(0xffffffffu, s, o);
    if (t == 0) out[0] = s * (1.0f / (float)(Bv * Mv));
}

// ---------------------------------------------------------------------------
extern "C" void kernel_launch(void* const* d_in, const int* in_sizes, int n_in,
                              void* d_out, int out_size) {
    const float* feats0 = (const float*)d_in[0];
    const float* feats1 = (const float*)d_in[1];
    const void*  corrs  = (const void*)d_in[2];
    int N = in_sizes[0] / (Bv * Dv);    // 20000

    static int smem_set = 0;
    if (!smem_set) {
        cudaFuncSetAttribute(logits_lse_kernel,
                             cudaFuncAttributeMaxDynamicSharedMemorySize, SMEM_TOTAL);
        smem_set = 1;
    }

    detect_dtype_kernel<<<1, 256>>>((const u64*)corrs, N);
    gather_norm_kernel<<<(2 * Bv * Mv) / 8, 256>>>(feats0, feats1, corrs, N);

    dim3 g2(8, NIT, Bv);                // 512 CTAs
    logits_lse_kernel<<<g2, THREADS, SMEM_TOTAL>>>();

    finalize1_kernel<<<NFIN, 256>>>();
    finalize2_kernel<<<1, 32>>>((float*)d_out);
}